// round 10
// baseline (speedup 1.0000x reference)
#include <cuda_runtime.h>
#include <cstdint>

// Quantized SiLU (per-row scales), S=8192 rows, H=4096 cols.
//   x_f   = x * scale_x[row]
//   y_q   = clip(rint(sigmoid(x_f) / scale_y[row]), -127, 127)
//   y_f   = y_q * scale_y[row]
//   out_q = clip(rint((x_f * y_f) / scale_out[row]), -127, 127)
//
// x is int8-valued => only 255 distinct inputs per row. Each CTA (one row)
// builds a flat 255-entry LUT of out_q in shared memory (exact math), then
// the 4096 row elements are index+LDS only. Flat layout is near the smem
// port floor (R8/R9 analysis: replication conserves port-bytes).
//
// R10 delta: 128 threads/CTA with 8 front-batched int4 loads per thread
// (MLP 4 -> 8 per warp, ~+45% outstanding loads chip-wide) to push DRAM
// utilization up from 68%. LUT build = 2 entries/thread, hidden under the
// in-flight loads. Everything else unchanged from the measured-best config.
//
// x arrives promoted to a 4-byte type (int32 or float32); values always in
// [-127,127], so the index decodes per element branch-free.
// Output: float32 [S*H out_q values][S scale_out values].

#define LOG2E 1.44269504088896340736f

// word -> LUT index in [0,254]
__device__ __forceinline__ int decode_idx(int w) {
    float fi = (float)w;                              // int32 interpretation
    int   wf = __float2int_rn(__int_as_float(w));     // float32 interpretation
    return ((fabsf(fi) > 127.5f) ? wf : w) + 127;
}

__device__ __forceinline__ float lut_entry(int i, float scale_x, float scale_y,
                                           float scale_o) {
    float f   = (float)(i - 127);
    float xf  = f * scale_x;
    float e   = exp2f(-xf * LOG2E);                   // exp(-x_f)
    float sig = __frcp_rn(1.0f + e);                  // sigmoid(x_f)
    float yq  = fminf(rintf(sig / scale_y), 127.0f);  // sigmoid>0: upper clip only
    float oq  = rintf(xf * (yq * scale_y) / scale_o);
    return fminf(fmaxf(oq, -127.0f), 127.0f);
}

__global__ void __launch_bounds__(128) silu_lut_kernel(
    const int4* __restrict__ x,
    const float* __restrict__ scale_x_v,
    const float* __restrict__ scale_y_v,
    const float* __restrict__ scale_out_v,
    float4* __restrict__ out,
    float* __restrict__ tail_dst,
    int write_tail)
{
    __shared__ float lut[255];
    int row = blockIdx.x;
    int t = threadIdx.x;

    // front-batch the row's loads (MLP=8, streaming) so they fly during LUT build
    long base = (long)row * 1024 + t;
    int4 v[8];
    #pragma unroll
    for (int k = 0; k < 8; k++)
        v[k] = __ldcs(x + base + 128 * k);

    float scale_x = __ldg(&scale_x_v[row]);
    float scale_y = __ldg(&scale_y_v[row]);
    float scale_o = __ldg(&scale_out_v[row]);

    // build LUT: entry i corresponds to xb = i - 127; 2 entries per thread.
    lut[t] = lut_entry(t, scale_x, scale_y, scale_o);
    if (t < 127)
        lut[t + 128] = lut_entry(t + 128, scale_x, scale_y, scale_o);
    if (write_tail && t == 0) tail_dst[row] = scale_o;
    __syncthreads();

    #pragma unroll
    for (int k = 0; k < 8; k++) {
        float4 r;
        r.x = lut[decode_idx(v[k].x)];
        r.y = lut[decode_idx(v[k].y)];
        r.z = lut[decode_idx(v[k].z)];
        r.w = lut[decode_idx(v[k].w)];
        __stcs(out + base + 128 * k, r);
    }
}

// Generic fallback for unexpected shapes (direct evaluation).
__device__ __forceinline__ float decode_elem(int w) {
    float fi = (float)w;
    float ff = __int_as_float(w);
    return (fabsf(fi) > 127.5f) ? ff : fi;
}

__global__ void __launch_bounds__(256) silu_quant_generic_kernel(
    const int* __restrict__ x,
    const float* __restrict__ scale_x_v,
    const float* __restrict__ scale_y_v,
    const float* __restrict__ scale_out_v,
    float* __restrict__ out,
    int H, long total)
{
    long i = (long)blockIdx.x * blockDim.x + threadIdx.x;
    if (i >= total) return;
    int row = (int)(i / H);
    float scale_x = scale_x_v[row];
    float scale_y = scale_y_v[row];
    float f   = decode_elem(x[i]);
    float xf  = f * scale_x;
    float e   = exp2f(-xf * LOG2E);
    float sig = __frcp_rn(1.0f + e);
    float yq  = fminf(rintf(sig / scale_y), 127.0f);
    float oq  = rintf(xf * (yq * scale_y) / scale_out_v[row]);
    out[i] = fminf(fmaxf(oq, -127.0f), 127.0f);
}

__global__ void tail_pad_kernel(const float* __restrict__ scale_o,
                                float* __restrict__ dst, int S, long extra) {
    long i = (long)blockIdx.x * blockDim.x + threadIdx.x;
    if (i >= extra) return;
    dst[i] = (i < S) ? scale_o[i] : 0.0f;
}

extern "C" void kernel_launch(void* const* d_in, const int* in_sizes, int n_in,
                              void* d_out, int out_size) {
    const void* x         = d_in[0];
    const float* scale_x  = (const float*)d_in[1];
    const float* scale_y  = (const float*)d_in[2];
    const float* scale_o  = (const float*)d_in[3];

    int S = in_sizes[1];            // rows (scale_x element count)
    int H = in_sizes[0] / S;        // cols
    long total = (long)S * H;
    long extra = (long)out_size - total;
    float* out = (float*)d_out;

    if (H == 4096) {
        int write_tail = (extra >= (long)S) ? 1 : 0;
        silu_lut_kernel<<<S, 128>>>(
            (const int4*)x, scale_x, scale_y, scale_o,
            (float4*)out, out + total, write_tail);
        if (extra > (long)S) {
            long pad = extra - S;
            tail_pad_kernel<<<(int)((pad + 255) / 256), 256>>>(
                scale_o + S, out + total + S, 0, pad);
        } else if (extra > 0 && !write_tail) {
            tail_pad_kernel<<<(int)((extra + 255) / 256), 256>>>(
                scale_o, out + total, (int)extra, extra);
        }
    } else {
        long blocks = (total + 255) / 256;
        silu_quant_generic_kernel<<<(unsigned)blocks, 256>>>(
            (const int*)x, scale_x, scale_y, scale_o, out, H, total);
        if (extra > 0) {
            tail_pad_kernel<<<(int)((extra + 255) / 256), 256>>>(
                scale_o, out + total, (int)(extra < S ? extra : S), extra);
        }
    }
}

// round 11
// speedup vs baseline: 1.0166x; 1.0166x over previous
#include <cuda_runtime.h>
#include <cstdint>

// Quantized SiLU (per-row scales), S=8192 rows, H=4096 cols.
//   x_f   = x * scale_x[row]
//   y_q   = clip(rint(sigmoid(x_f) / scale_y[row]), -127, 127)
//   y_f   = y_q * scale_y[row]
//   out_q = clip(rint((x_f * y_f) / scale_out[row]), -127, 127)
//
// x is int8-valued => only 255 distinct inputs per row. Each CTA (one row)
// builds a flat 255-entry LUT of out_q in shared memory (exact math), then
// the 4096 row elements are index+LDS only.
//
// R11 structure (combining R7's occupancy with R10's load depth):
//   128 threads/CTA; batch A (4 int4 loads) issued FRONT, in flight during
//   the LUT build + barrier; batch B (4 int4 loads) issued right after the
//   barrier, overlapping batch A's LDS+stores. Peak live loads per thread
//   stays ~4-5 regs' worth instead of 8 across the barrier (R10: 53 regs,
//   occ 50.6%). Streaming hints kept (measured neutral, never harmful).
//
// x arrives promoted to a 4-byte type (int32 or float32); values always in
// [-127,127], so the index decodes per element branch-free.
// Output: float32 [S*H out_q values][S scale_out values].

#define LOG2E 1.44269504088896340736f

// word -> LUT index in [0,254]
__device__ __forceinline__ int decode_idx(int w) {
    float fi = (float)w;                              // int32 interpretation
    int   wf = __float2int_rn(__int_as_float(w));     // float32 interpretation
    return ((fabsf(fi) > 127.5f) ? wf : w) + 127;
}

__device__ __forceinline__ float lut_entry(int i, float scale_x, float scale_y,
                                           float scale_o) {
    float f   = (float)(i - 127);
    float xf  = f * scale_x;
    float e   = exp2f(-xf * LOG2E);                   // exp(-x_f)
    float sig = __frcp_rn(1.0f + e);                  // sigmoid(x_f)
    float yq  = fminf(rintf(sig / scale_y), 127.0f);  // sigmoid>0: upper clip only
    float oq  = rintf(xf * (yq * scale_y) / scale_o);
    return fminf(fmaxf(oq, -127.0f), 127.0f);
}

__global__ void __launch_bounds__(128) silu_lut_kernel(
    const int4* __restrict__ x,
    const float* __restrict__ scale_x_v,
    const float* __restrict__ scale_y_v,
    const float* __restrict__ scale_out_v,
    float4* __restrict__ out,
    float* __restrict__ tail_dst,
    int write_tail)
{
    __shared__ float lut[255];
    int row = blockIdx.x;
    int t = threadIdx.x;

    long base = (long)row * 1024 + t;

    // Batch A: 4 front-batched loads, in flight during LUT build + barrier
    int4 a0 = __ldcs(x + base);
    int4 a1 = __ldcs(x + base + 128);
    int4 a2 = __ldcs(x + base + 256);
    int4 a3 = __ldcs(x + base + 384);

    float scale_x = __ldg(&scale_x_v[row]);
    float scale_y = __ldg(&scale_y_v[row]);
    float scale_o = __ldg(&scale_out_v[row]);

    // Build LUT: entry i corresponds to xb = i - 127; 2 entries per thread.
    lut[t] = lut_entry(t, scale_x, scale_y, scale_o);
    if (t < 127)
        lut[t + 128] = lut_entry(t + 128, scale_x, scale_y, scale_o);
    if (write_tail && t == 0) tail_dst[row] = scale_o;
    __syncthreads();

    // Batch B: issue immediately after barrier; overlaps batch A processing.
    int4 b0 = __ldcs(x + base + 512);
    int4 b1 = __ldcs(x + base + 640);
    int4 b2 = __ldcs(x + base + 768);
    int4 b3 = __ldcs(x + base + 896);

    float4 r;
    r.x = lut[decode_idx(a0.x)]; r.y = lut[decode_idx(a0.y)];
    r.z = lut[decode_idx(a0.z)]; r.w = lut[decode_idx(a0.w)];
    __stcs(out + base, r);
    r.x = lut[decode_idx(a1.x)]; r.y = lut[decode_idx(a1.y)];
    r.z = lut[decode_idx(a1.z)]; r.w = lut[decode_idx(a1.w)];
    __stcs(out + base + 128, r);
    r.x = lut[decode_idx(a2.x)]; r.y = lut[decode_idx(a2.y)];
    r.z = lut[decode_idx(a2.z)]; r.w = lut[decode_idx(a2.w)];
    __stcs(out + base + 256, r);
    r.x = lut[decode_idx(a3.x)]; r.y = lut[decode_idx(a3.y)];
    r.z = lut[decode_idx(a3.z)]; r.w = lut[decode_idx(a3.w)];
    __stcs(out + base + 384, r);

    r.x = lut[decode_idx(b0.x)]; r.y = lut[decode_idx(b0.y)];
    r.z = lut[decode_idx(b0.z)]; r.w = lut[decode_idx(b0.w)];
    __stcs(out + base + 512, r);
    r.x = lut[decode_idx(b1.x)]; r.y = lut[decode_idx(b1.y)];
    r.z = lut[decode_idx(b1.z)]; r.w = lut[decode_idx(b1.w)];
    __stcs(out + base + 640, r);
    r.x = lut[decode_idx(b2.x)]; r.y = lut[decode_idx(b2.y)];
    r.z = lut[decode_idx(b2.z)]; r.w = lut[decode_idx(b2.w)];
    __stcs(out + base + 768, r);
    r.x = lut[decode_idx(b3.x)]; r.y = lut[decode_idx(b3.y)];
    r.z = lut[decode_idx(b3.z)]; r.w = lut[decode_idx(b3.w)];
    __stcs(out + base + 896, r);
}

// Generic fallback for unexpected shapes (direct evaluation).
__device__ __forceinline__ float decode_elem(int w) {
    float fi = (float)w;
    float ff = __int_as_float(w);
    return (fabsf(fi) > 127.5f) ? ff : fi;
}

__global__ void __launch_bounds__(256) silu_quant_generic_kernel(
    const int* __restrict__ x,
    const float* __restrict__ scale_x_v,
    const float* __restrict__ scale_y_v,
    const float* __restrict__ scale_out_v,
    float* __restrict__ out,
    int H, long total)
{
    long i = (long)blockIdx.x * blockDim.x + threadIdx.x;
    if (i >= total) return;
    int row = (int)(i / H);
    float scale_x = scale_x_v[row];
    float scale_y = scale_y_v[row];
    float f   = decode_elem(x[i]);
    float xf  = f * scale_x;
    float e   = exp2f(-xf * LOG2E);
    float sig = __frcp_rn(1.0f + e);
    float yq  = fminf(rintf(sig / scale_y), 127.0f);
    float oq  = rintf(xf * (yq * scale_y) / scale_out_v[row]);
    out[i] = fminf(fmaxf(oq, -127.0f), 127.0f);
}

__global__ void tail_pad_kernel(const float* __restrict__ scale_o,
                                float* __restrict__ dst, int S, long extra) {
    long i = (long)blockIdx.x * blockDim.x + threadIdx.x;
    if (i >= extra) return;
    dst[i] = (i < S) ? scale_o[i] : 0.0f;
}

extern "C" void kernel_launch(void* const* d_in, const int* in_sizes, int n_in,
                              void* d_out, int out_size) {
    const void* x         = d_in[0];
    const float* scale_x  = (const float*)d_in[1];
    const float* scale_y  = (const float*)d_in[2];
    const float* scale_o  = (const float*)d_in[3];

    int S = in_sizes[1];            // rows (scale_x element count)
    int H = in_sizes[0] / S;        // cols
    long total = (long)S * H;
    long extra = (long)out_size - total;
    float* out = (float*)d_out;

    if (H == 4096) {
        int write_tail = (extra >= (long)S) ? 1 : 0;
        silu_lut_kernel<<<S, 128>>>(
            (const int4*)x, scale_x, scale_y, scale_o,
            (float4*)out, out + total, write_tail);
        if (extra > (long)S) {
            long pad = extra - S;
            tail_pad_kernel<<<(int)((pad + 255) / 256), 256>>>(
                scale_o + S, out + total + S, 0, pad);
        } else if (extra > 0 && !write_tail) {
            tail_pad_kernel<<<(int)((extra + 255) / 256), 256>>>(
                scale_o, out + total, (int)extra, extra);
        }
    } else {
        long blocks = (total + 255) / 256;
        silu_quant_generic_kernel<<<(unsigned)blocks, 256>>>(
            (const int*)x, scale_x, scale_y, scale_o, out, H, total);
        if (extra > 0) {
            tail_pad_kernel<<<(int)((extra + 255) / 256), 256>>>(
                scale_o, out + total, (int)(extra < S ? extra : S), extra);
        }
    }
}